// round 1
// baseline (speedup 1.0000x reference)
#include <cuda_runtime.h>
#include <cstdint>

#define BB 4
#define HH 16
#define SSZ 2048
#define DH 64
#define TQ 64
#define TK 64
#define NTHREADS 128

// shared memory layout (in 32-bit words)
// QP: [32 dpairs][65 float2]  (pair stride 65 f2 = 130 words) -> 4160 words
// KP: same                                                   -> 4160 words
// VT: [64 d][66 floats] (k contiguous)                       -> 4224 words
// ES: [64 q][66 floats] (k contiguous)                       -> 4224 words
// RED:[64 q][17 floats]                                      -> 1088 words
#define QP_OFF   0
#define KP_OFF   4160
#define VT_OFF   8320
#define ES_OFF   12544
#define RED_OFF  16768
#define SMEM_WORDS 17856

typedef unsigned long long u64;

__device__ __forceinline__ u64 ffma2(u64 a, u64 b, u64 c) {
    u64 d;
    asm("fma.rn.f32x2 %0, %1, %2, %3;" : "=l"(d) : "l"(a), "l"(b), "l"(c));
    return d;
}
__device__ __forceinline__ float lo32(u64 v) { return __uint_as_float((unsigned)v); }
__device__ __forceinline__ float hi32(u64 v) { return __uint_as_float((unsigned)(v >> 32)); }

// FMA-only expf: ~1e-7 rel error on the score range we see (|x| < ~40).
// Avoids MUFU (rt 8/SMSP would make 268M exps cost ~2ms chip-wide).
__device__ __forceinline__ float fexp(float x) {
    x = fmaxf(x, -80.0f);
    float t = fmaf(x, 1.4426950408889634f, 12582912.0f); // round(x*log2e) in low mantissa
    int ni = __float_as_int(t) << 23;                    // n << 23 exactly
    float n = t - 12582912.0f;
    float r = fmaf(n, -0.693359375f, x);                 // ln2 hi/lo split
    r = fmaf(n, 2.12194440e-4f, r);
    float p = 1.3888889e-3f;                             // Taylor deg 6 on |r|<=0.347
    p = fmaf(p, r, 8.3333333e-3f);
    p = fmaf(p, r, 4.1666668e-2f);
    p = fmaf(p, r, 1.6666667e-1f);
    p = fmaf(p, r, 0.5f);
    p = fmaf(p, r, 1.0f);
    p = fmaf(p, r, 1.0f);
    return __int_as_float(__float_as_int(p) + ni);       // * 2^n via exponent bits
}

extern __shared__ float sm[];

__global__ void __launch_bounds__(NTHREADS)
attn_fused_kernel(const float* __restrict__ Q, const float* __restrict__ K,
                  const float* __restrict__ V, const int* __restrict__ M,
                  float* __restrict__ Og, float* __restrict__ Pg,
                  int wout, int wp)
{
    const int tid = threadIdx.x;
    const int tx = tid & 15;   // 16 lanes: k (GEMM1) / d (GEMM2)
    const int ty = tid >> 4;   // 8 groups: 8 q rows each
    const int q0 = blockIdx.x * TQ;
    const int h  = blockIdx.y;
    const int b  = blockIdx.z;
    const size_t bh = (size_t)b * HH + h;

    const float* Qg  = Q + (bh * SSZ + (size_t)q0) * DH;
    const float* Kg0 = K + bh * SSZ * DH;
    const float* Vg0 = V + bh * SSZ * DH;
    const int*   Mg  = M + ((size_t)b * SSZ + (size_t)q0) * SSZ;

    float2* QPs = (float2*)(sm + QP_OFF);
    float2* KPs = (float2*)(sm + KP_OFF);
    float*  VTs = sm + VT_OFF;
    float*  ESs = sm + ES_OFF;
    float*  RED = sm + RED_OFF;

    // ---- load Q tile once: QP[p][q] = (Q[q][2p], Q[q][2p+1]) ----
    #pragma unroll
    for (int it = 0; it < 8; it++) {
        int idx = tid + NTHREADS * it;          // 1024 float4s total
        int r = idx >> 4, c = idx & 15;         // r = q row, c = float4 col
        float4 v = *(const float4*)(Qg + r * DH + c * 4);
        QPs[(2 * c) * 65 + r]     = make_float2(v.x, v.y);
        QPs[(2 * c + 1) * 65 + r] = make_float2(v.z, v.w);
    }

    u64 acc2[8][4];
    #pragma unroll
    for (int i = 0; i < 8; i++)
        #pragma unroll
        for (int dd = 0; dd < 4; dd++) acc2[i][dd] = 0ULL;
    float rs[8];
    #pragma unroll
    for (int i = 0; i < 8; i++) rs[i] = 0.0f;

    const u64* QPu = (const u64*)QPs;
    const u64* KPu = (const u64*)KPs;
    const u64* ESu = (const u64*)ESs;
    const u64* VTu = (const u64*)VTs;

    for (int t = 0; t < SSZ / TK; t++) {
        const int k0 = t * TK;
        const float* Kg = Kg0 + (size_t)k0 * DH;
        const float* Vg = Vg0 + (size_t)k0 * DH;

        // ---- load K tile (d-paired) + V tile (transposed [d][k]) ----
        #pragma unroll
        for (int it = 0; it < 8; it++) {
            int idx = tid + NTHREADS * it;
            int r = idx >> 4, c = idx & 15;
            float4 kv = *(const float4*)(Kg + r * DH + c * 4);
            KPs[(2 * c) * 65 + r]     = make_float2(kv.x, kv.y);
            KPs[(2 * c + 1) * 65 + r] = make_float2(kv.z, kv.w);
            float4 vv = *(const float4*)(Vg + r * DH + c * 4);
            VTs[(4 * c + 0) * 66 + r] = vv.x;
            VTs[(4 * c + 1) * 66 + r] = vv.y;
            VTs[(4 * c + 2) * 66 + r] = vv.z;
            VTs[(4 * c + 3) * 66 + r] = vv.w;
        }
        __syncthreads();

        // ---- GEMM1: S = Q K^T, packed over d-pairs ----
        u64 acc1[8][4];
        #pragma unroll
        for (int i = 0; i < 8; i++)
            #pragma unroll
            for (int j = 0; j < 4; j++) acc1[i][j] = 0ULL;

        #pragma unroll 8
        for (int p = 0; p < 32; p++) {
            u64 a[8], bb[4];
            #pragma unroll
            for (int i = 0; i < 8; i++) a[i] = QPu[p * 65 + 8 * ty + i];
            #pragma unroll
            for (int j = 0; j < 4; j++) bb[j] = KPu[p * 65 + tx + 16 * j];
            #pragma unroll
            for (int i = 0; i < 8; i++)
                #pragma unroll
                for (int j = 0; j < 4; j++)
                    acc1[i][j] = ffma2(a[i], bb[j], acc1[i][j]);
        }

        // ---- mask + exp; stash e in smem (for PV) and gmem (unnormalized p) ----
        #pragma unroll
        for (int i = 0; i < 8; i++) {
            const int q = 8 * ty + i;
            const int* mrow = Mg + (size_t)q * SSZ + k0;
            const size_t poff = (bh * SSZ + (size_t)(q0 + q)) * SSZ + (size_t)k0;
            #pragma unroll
            for (int j = 0; j < 4; j++) {
                int kk = tx + 16 * j;
                float s = (lo32(acc1[i][j]) + hi32(acc1[i][j])) * 0.125f;
                float e = (mrow[kk] == 1) ? 0.0f : fexp(s);
                rs[i] += e;
                ESs[q * 66 + kk] = e;
                if (wp) Pg[poff + kk] = e;
            }
        }
        __syncthreads();

        // ---- GEMM2: out_acc += E V, packed over k-pairs ----
        #pragma unroll 8
        for (int kp = 0; kp < 32; kp++) {
            u64 a[8], bb[4];
            #pragma unroll
            for (int i = 0; i < 8; i++) a[i] = ESu[(8 * ty + i) * 33 + kp];
            #pragma unroll
            for (int dd = 0; dd < 4; dd++) bb[dd] = VTu[(tx + 16 * dd) * 33 + kp];
            #pragma unroll
            for (int i = 0; i < 8; i++)
                #pragma unroll
                for (int dd = 0; dd < 4; dd++)
                    acc2[i][dd] = ffma2(a[i], bb[dd], acc2[i][dd]);
        }
        __syncthreads();
    }

    // ---- row sums -> 1/sum ----
    #pragma unroll
    for (int i = 0; i < 8; i++) RED[(8 * ty + i) * 17 + tx] = rs[i];
    __syncthreads();
    if (tid < 64) {
        float s = 0.0f;
        #pragma unroll
        for (int t2 = 0; t2 < 16; t2++) s += RED[tid * 17 + t2];
        RED[tid * 17 + 16] = (s > 0.0f) ? (1.0f / s) : 0.0f;
    }
    __syncthreads();
    float inv[8];
    #pragma unroll
    for (int i = 0; i < 8; i++) inv[i] = RED[(8 * ty + i) * 17 + 16];

    // ---- write out = (E V) / rowsum ----
    if (wout) {
        #pragma unroll
        for (int i = 0; i < 8; i++) {
            const size_t obase = (bh * SSZ + (size_t)(q0 + 8 * ty + i)) * DH;
            #pragma unroll
            for (int dd = 0; dd < 4; dd++) {
                float o = (lo32(acc2[i][dd]) + hi32(acc2[i][dd])) * inv[i];
                Og[obase + tx + 16 * dd] = o;
            }
        }
    }

    // ---- normalize this block's own p_attn slice in place (L2-resident RMW) ----
    if (wp) {
        size_t rb[8];
        #pragma unroll
        for (int i = 0; i < 8; i++)
            rb[i] = (bh * SSZ + (size_t)(q0 + 8 * ty + i)) * SSZ;
        for (int m = 0; m < 128; m++) {
            int kk = tx + 16 * m;
            #pragma unroll
            for (int i = 0; i < 8; i++)
                Pg[rb[i] + kk] *= inv[i];
        }
    }
}

extern "C" void kernel_launch(void* const* d_in, const int* in_sizes, int n_in,
                              void* d_out, int out_size) {
    const float* Q = (const float*)d_in[0];
    const float* K = (const float*)d_in[1];
    const float* V = (const float*)d_in[2];
    const int*   M = (const int*)d_in[3];

    const long long OUTE = (long long)BB * HH * SSZ * DH;   // 8,388,608
    const long long PE   = (long long)BB * HH * SSZ * SSZ;  // 268,435,456

    float* Og = nullptr; float* Pg = nullptr;
    int wout = 0, wp = 0;
    long long osz = (long long)out_size;
    if (osz >= OUTE + PE) { Og = (float*)d_out; Pg = Og + OUTE; wout = 1; wp = 1; }
    else if (osz == PE)   { Pg = (float*)d_out; wp = 1; }
    else                  { Og = (float*)d_out; wout = 1; }

    cudaFuncSetAttribute(attn_fused_kernel,
                         cudaFuncAttributeMaxDynamicSharedMemorySize,
                         SMEM_WORDS * 4);

    dim3 grid(SSZ / TQ, HH, BB);
    attn_fused_kernel<<<grid, NTHREADS, SMEM_WORDS * 4>>>(Q, K, V, M, Og, Pg, wout, wp);
}

// round 3
// speedup vs baseline: 2.5095x; 2.5095x over previous
#include <cuda_runtime.h>
#include <cuda_bf16.h>
#include <cstdint>

#define BB 4
#define HH 16
#define SSZ 2048
#define DH 64
#define TQ 64
#define TK 64
#define NTH 128
#define NT (SSZ / TK)

// bf16 tiles: 64 rows x (64 + 8 pad) elems -> 144-byte row stride
#define ROWB 144
#define HALF_OFF 9216          /* hi -> lo region offset (64*144) */
#define REG_KQ 0               /* Khi/Klo (Q overlays before loop) */
#define REG_V  18432           /* Vhi/Vlo */
#define REG_RED 36864          /* 64 floats: 1/rowsum */
#define SM_BYTES 37376

// ---------------- PTX helpers (base compute_103 features only) ----------------
__device__ __forceinline__ uint32_t smem_u32(const void* p) {
    uint32_t a;
    asm("{ .reg .u64 t; cvta.to.shared.u64 t, %1; cvt.u32.u64 %0, t; }" : "=r"(a) : "l"(p));
    return a;
}
__device__ __forceinline__ void ldsm4(unsigned* r, uint32_t a) {
    asm volatile("ldmatrix.sync.aligned.m8n8.x4.shared.b16 {%0,%1,%2,%3}, [%4];"
        : "=r"(r[0]), "=r"(r[1]), "=r"(r[2]), "=r"(r[3]) : "r"(a));
}
__device__ __forceinline__ void ldsm4t(unsigned* r, uint32_t a) {
    asm volatile("ldmatrix.sync.aligned.m8n8.x4.trans.shared.b16 {%0,%1,%2,%3}, [%4];"
        : "=r"(r[0]), "=r"(r[1]), "=r"(r[2]), "=r"(r[3]) : "r"(a));
}
__device__ __forceinline__ void hmma(float* c, const unsigned* a, unsigned b0, unsigned b1) {
    asm volatile("mma.sync.aligned.m16n8k16.row.col.f32.bf16.bf16.f32 "
        "{%0,%1,%2,%3}, {%4,%5,%6,%7}, {%8,%9}, {%0,%1,%2,%3};"
        : "+f"(c[0]), "+f"(c[1]), "+f"(c[2]), "+f"(c[3])
        : "r"(a[0]), "r"(a[1]), "r"(a[2]), "r"(a[3]), "r"(b0), "r"(b1));
}
#define STS128(addr, v) \
    asm volatile("st.shared.v4.b32 [%0], {%1,%2,%3,%4};" \
        :: "r"((uint32_t)(addr)), "r"((v).x), "r"((v).y), "r"((v).z), "r"((v).w) : "memory")

__device__ __forceinline__ unsigned cvt2(float hi, float lo) {
    unsigned r; asm("cvt.rn.bf16x2.f32 %0, %1, %2;" : "=r"(r) : "f"(hi), "f"(lo));
    return r;
}
// split pair (a,b) -> hi bf16x2 {b,a}, lo bf16x2 of residuals
__device__ __forceinline__ void split2(float a, float b, unsigned& h, unsigned& l) {
    h = cvt2(b, a);
    float ra = a - __uint_as_float(h << 16);
    float rb = b - __uint_as_float(h & 0xFFFF0000u);
    l = cvt2(rb, ra);
}
// 8 consecutive floats -> hi uint4 / lo uint4 (bf16x2 each)
__device__ __forceinline__ void split8(float4 x, float4 y, uint4& hi, uint4& lo) {
    split2(x.x, x.y, hi.x, lo.x);
    split2(x.z, x.w, hi.y, lo.y);
    split2(y.x, y.y, hi.z, lo.z);
    split2(y.z, y.w, hi.w, lo.w);
}

// FMA-only expf (avoids MUFU throughput limit: 268M exps)
__device__ __forceinline__ float fexp(float x) {
    x = fmaxf(x, -80.0f);
    float t = fmaf(x, 1.4426950408889634f, 12582912.0f);
    int ni = __float_as_int(t) << 23;
    float n = t - 12582912.0f;
    float r = fmaf(n, -0.693359375f, x);
    r = fmaf(n, 2.12194440e-4f, r);
    float p = 1.3888889e-3f;
    p = fmaf(p, r, 8.3333333e-3f);
    p = fmaf(p, r, 4.1666668e-2f);
    p = fmaf(p, r, 1.6666667e-1f);
    p = fmaf(p, r, 0.5f);
    p = fmaf(p, r, 1.0f);
    p = fmaf(p, r, 1.0f);
    return __int_as_float(__float_as_int(p) + ni);
}

extern __shared__ char smem[];

__global__ void __launch_bounds__(NTH)
attn_hmma_kernel(const float* __restrict__ Q, const float* __restrict__ K,
                 const float* __restrict__ V, const int* __restrict__ M,
                 float* __restrict__ Og, float* __restrict__ Pg,
                 int wout, int wp)
{
    const uint32_t sb = smem_u32(smem);
    const int tid = threadIdx.x;
    const int lane = tid & 31, w = tid >> 5;
    const int q0 = blockIdx.x * TQ;
    const int hh = blockIdx.y, b = blockIdx.z;
    const size_t bh = (size_t)b * HH + hh;

    const float* Qg  = Q + (bh * SSZ + (size_t)q0) * DH;
    const float* Kg0 = K + bh * SSZ * DH;
    const float* Vg0 = V + bh * SSZ * DH;
    const int*   Mg0 = M + ((size_t)b * SSZ + (size_t)q0) * SSZ;

    // ---- Q tile fill (into K region, consumed to regs before K overwrites) ----
    #pragma unroll
    for (int it = 0; it < 4; it++) {
        int idx = tid + NTH * it;        // 512 chunks of 8 floats
        int row = idx >> 3, g = idx & 7;
        float4 x = *(const float4*)(Qg + row * DH + 8 * g);
        float4 y = *(const float4*)(Qg + row * DH + 8 * g + 4);
        uint4 hi, lo; split8(x, y, hi, lo);
        uint32_t a = sb + REG_KQ + row * ROWB + g * 16;
        STS128(a, hi);
        STS128(a + HALF_OFF, lo);
    }
    __syncthreads();

    // ---- Q fragments, register resident for whole k-loop ----
    unsigned qh[4][4], ql[4][4];
    {
        int row = 16 * w + (lane & 15);
        int colb = ((lane >> 4) << 4);   // (lane>>4)*8 elems * 2B
        #pragma unroll
        for (int c = 0; c < 4; c++) {
            uint32_t a = sb + REG_KQ + row * ROWB + c * 32 + colb;
            ldsm4(qh[c], a);
            ldsm4(ql[c], a + HALF_OFF);
        }
    }

    float oacc[8][4];
    #pragma unroll
    for (int j = 0; j < 8; j++)
        #pragma unroll
        for (int i = 0; i < 4; i++) oacc[j][i] = 0.0f;
    float rs0 = 0.0f, rs1 = 0.0f;

    const int r0 = 16 * w + (lane >> 2);     // local q row (first half)
    const int cbase = 2 * (lane & 3);
    const int* mR0 = Mg0 + (size_t)r0 * SSZ;
    const int* mR1 = mR0 + (size_t)8 * SSZ;
    float* pR0 = Pg + (bh * SSZ + (size_t)(q0 + r0)) * SSZ;
    float* pR1 = pR0 + (size_t)8 * SSZ;

    // precomputed ldmatrix lane-address components
    const int krow_l = ((lane >> 4) << 3) + (lane & 7);      // GEMM1 K
    const int kcolb_l = ((lane >> 3) & 1) << 4;
    const int vrow_l = (((lane >> 3) & 1) << 3) + (lane & 7); // GEMM2 V
    const int vcolb_l = (lane >> 4) << 4;

    #pragma unroll 1
    for (int t = 0; t < NT; t++) {
        const int k0 = t * TK;
        __syncthreads();   // previous tile fully consumed

        // ---- K / V tile fill (f32 -> bf16 hi/lo) ----
        const float* Kg = Kg0 + (size_t)k0 * DH;
        const float* Vg = Vg0 + (size_t)k0 * DH;
        #pragma unroll
        for (int it = 0; it < 4; it++) {
            int idx = tid + NTH * it;
            int row = idx >> 3, g = idx & 7;
            float4 x = *(const float4*)(Kg + row * DH + 8 * g);
            float4 y = *(const float4*)(Kg + row * DH + 8 * g + 4);
            uint4 hi, lo; split8(x, y, hi, lo);
            uint32_t a = sb + REG_KQ + row * ROWB + g * 16;
            STS128(a, hi);
            STS128(a + HALF_OFF, lo);
            x = *(const float4*)(Vg + row * DH + 8 * g);
            y = *(const float4*)(Vg + row * DH + 8 * g + 4);
            split8(x, y, hi, lo);
            a = sb + REG_V + row * ROWB + g * 16;
            STS128(a, hi);
            STS128(a + HALF_OFF, lo);
        }
        __syncthreads();

        // ---- GEMM1: S = Q K^T (3-term bf16 split) ----
        float sc[8][4];
        #pragma unroll
        for (int j = 0; j < 8; j++)
            #pragma unroll
            for (int i = 0; i < 4; i++) sc[j][i] = 0.0f;

        #pragma unroll
        for (int c = 0; c < 4; c++) {
            #pragma unroll
            for (int p = 0; p < 4; p++) {
                unsigned kh[4], kl[4];
                uint32_t a = sb + REG_KQ + (16 * p + krow_l) * ROWB + c * 32 + kcolb_l;
                ldsm4(kh, a);
                ldsm4(kl, a + HALF_OFF);
                hmma(sc[2 * p],     qh[c], kh[0], kh[1]);
                hmma(sc[2 * p + 1], qh[c], kh[2], kh[3]);
                hmma(sc[2 * p],     qh[c], kl[0], kl[1]);
                hmma(sc[2 * p + 1], qh[c], kl[2], kl[3]);
                hmma(sc[2 * p],     ql[c], kh[0], kh[1]);
                hmma(sc[2 * p + 1], ql[c], kh[2], kh[3]);
            }
        }

        // ---- mask + exp + p-write + rowsum (C-frag layout) ----
        #pragma unroll
        for (int j = 0; j < 8; j++) {
            int col = k0 + 8 * j + cbase;
            int2 m0 = *(const int2*)(mR0 + col);
            int2 m1 = *(const int2*)(mR1 + col);
            float e0 = (m0.x == 1) ? 0.0f : fexp(sc[j][0] * 0.125f);
            float e1 = (m0.y == 1) ? 0.0f : fexp(sc[j][1] * 0.125f);
            float e2 = (m1.x == 1) ? 0.0f : fexp(sc[j][2] * 0.125f);
            float e3 = (m1.y == 1) ? 0.0f : fexp(sc[j][3] * 0.125f);
            rs0 += e0 + e1;
            rs1 += e2 + e3;
            if (wp) {
                *(float2*)(pR0 + col) = make_float2(e0, e1);
                *(float2*)(pR1 + col) = make_float2(e2, e3);
            }
            sc[j][0] = e0; sc[j][1] = e1; sc[j][2] = e2; sc[j][3] = e3;
        }

        // ---- in-register relayout: S C-frags -> GEMM2 A-frags (hi/lo) ----
        unsigned pah[4][4], pal[4][4];
        #pragma unroll
        for (int c = 0; c < 4; c++) {
            split2(sc[2 * c][0],     sc[2 * c][1],     pah[c][0], pal[c][0]);
            split2(sc[2 * c][2],     sc[2 * c][3],     pah[c][1], pal[c][1]);
            split2(sc[2 * c + 1][0], sc[2 * c + 1][1], pah[c][2], pal[c][2]);
            split2(sc[2 * c + 1][2], sc[2 * c + 1][3], pah[c][3], pal[c][3]);
        }

        // ---- GEMM2: O += P V (V via ldmatrix.trans, 3-term split) ----
        #pragma unroll
        for (int c = 0; c < 4; c++) {
            #pragma unroll
            for (int p = 0; p < 4; p++) {
                unsigned vh[4], vl[4];
                uint32_t a = sb + REG_V + (16 * c + vrow_l) * ROWB + p * 32 + vcolb_l;
                ldsm4t(vh, a);
                ldsm4t(vl, a + HALF_OFF);
                hmma(oacc[2 * p],     pah[c], vh[0], vh[1]);
                hmma(oacc[2 * p + 1], pah[c], vh[2], vh[3]);
                hmma(oacc[2 * p],     pah[c], vl[0], vl[1]);
                hmma(oacc[2 * p + 1], pah[c], vl[2], vl[3]);
                hmma(oacc[2 * p],     pal[c], vh[0], vh[1]);
                hmma(oacc[2 * p + 1], pal[c], vh[2], vh[3]);
            }
        }
    }

    // ---- row sums across quad lanes ----
    rs0 += __shfl_xor_sync(0xFFFFFFFFu, rs0, 1);
    rs0 += __shfl_xor_sync(0xFFFFFFFFu, rs0, 2);
    rs1 += __shfl_xor_sync(0xFFFFFFFFu, rs1, 1);
    rs1 += __shfl_xor_sync(0xFFFFFFFFu, rs1, 2);
    const float inv0 = (rs0 > 0.0f) ? (1.0f / rs0) : 0.0f;
    const float inv1 = (rs1 > 0.0f) ? (1.0f / rs1) : 0.0f;

    if (wout) {
        float* oR0 = Og + (bh * SSZ + (size_t)(q0 + r0)) * DH;
        float* oR1 = oR0 + (size_t)8 * DH;
        #pragma unroll
        for (int j = 0; j < 8; j++) {
            *(float2*)(oR0 + 8 * j + cbase) = make_float2(oacc[j][0] * inv0, oacc[j][1] * inv0);
            *(float2*)(oR1 + 8 * j + cbase) = make_float2(oacc[j][2] * inv1, oacc[j][3] * inv1);
        }
    }

    if (wp) {
        float* sred = (float*)(smem + REG_RED);
        if ((lane & 3) == 0) { sred[r0] = inv0; sred[r0 + 8] = inv1; }
        __syncthreads();
        float4* pr = (float4*)(Pg + (bh * SSZ + (size_t)q0) * SSZ);
        #pragma unroll 8
        for (int i = 0; i < (TQ * SSZ / 4) / NTH; i++) {
            int idx = tid + NTH * i;
            float iv = sred[idx >> 9];
            float4 v = pr[idx];
            v.x *= iv; v.y *= iv; v.z *= iv; v.w *= iv;
            pr[idx] = v;
        }
    }
}

extern "C" void kernel_launch(void* const* d_in, const int* in_sizes, int n_in,
                              void* d_out, int out_size) {
    const float* Q = (const float*)d_in[0];
    const float* K = (const float*)d_in[1];
    const float* V = (const float*)d_in[2];
    const int*   M = (const int*)d_in[3];

    const long long OUTE = (long long)BB * HH * SSZ * DH;
    const long long PE   = (long long)BB * HH * SSZ * SSZ;

    float* Og = nullptr; float* Pg = nullptr;
    int wout = 0, wp = 0;
    long long osz = (long long)out_size;
    if (osz >= OUTE + PE) { Og = (float*)d_out; Pg = Og + OUTE; wout = 1; wp = 1; }
    else if (osz == PE)   { Pg = (float*)d_out; wp = 1; }
    else                  { Og = (float*)d_out; wout = 1; }

    dim3 grid(SSZ / TQ, HH, BB);
    attn_hmma_kernel<<<grid, NTH, SM_BYTES>>>(Q, K, V, M, Og, Pg, wout, wp);
}